// round 11
// baseline (speedup 1.0000x reference)
#include <cuda_runtime.h>
#include <cuda_bf16.h>
#include <cstdint>
#include <math.h>

// ---------------- problem constants ----------------
constexpr int T_TOK = 401408;      // 8*224*224 tokens (= 8192 windows * 49)

// ---------------- scratch (device globals: no cudaMalloc allowed) ----------------
__device__ __align__(16) __nv_bfloat16 g_qkv [(size_t)T_TOK * 576];
__device__ __align__(16) __nv_bfloat16 g_attn[(size_t)T_TOK * 192];
__device__ __align__(16) __nv_bfloat16 g_m   [(size_t)T_TOK * 192];
__device__ __align__(16) __nv_bfloat16 g_hid [(size_t)T_TOK * 768];
__device__ __align__(16) __nv_bfloat16 g_wqkv[192 * 576];
__device__ __align__(16) __nv_bfloat16 g_wproj[192 * 192];
__device__ __align__(16) __nv_bfloat16 g_w1  [192 * 768];
__device__ __align__(16) __nv_bfloat16 g_w2  [768 * 192];

// ---------------- row mapping: window row -> image row ----------------
__device__ __forceinline__ int maprow(int r) {
    int w  = r / 49;
    int t  = r - w * 49;
    int wb = w >> 10;
    int wi = w & 1023;
    int wh = wi >> 5;
    int ww = wi & 31;
    int th = t / 7;
    int tw = t - th * 7;
    int h  = wh * 7 + th + 3; if (h  >= 224) h  -= 224;
    int wc = ww * 7 + tw + 3; if (wc >= 224) wc -= 224;
    return wb * 50176 + h * 224 + wc;
}

// ---------------- tiny helpers ----------------
__global__ void convert_kernel(const float* __restrict__ s, __nv_bfloat16* __restrict__ d, int n) {
    int i = blockIdx.x * blockDim.x + threadIdx.x;
    if (i < n) d[i] = __float2bfloat16(s[i]);
}

__device__ __forceinline__ void cp16(uint32_t smaddr, const void* g) {
    asm volatile("cp.async.cg.shared.global [%0],[%1],16;\n" :: "r"(smaddr), "l"(g));
}
__device__ __forceinline__ void cp_commit() { asm volatile("cp.async.commit_group;\n"); }
template <int N> __device__ __forceinline__ void cp_wait() {
    asm volatile("cp.async.wait_group %0;\n" :: "n"(N));
}
__device__ __forceinline__ void ldm_x4(uint32_t& r0, uint32_t& r1, uint32_t& r2, uint32_t& r3,
                                       uint32_t addr) {
    asm volatile("ldmatrix.sync.aligned.m8n8.x4.shared.b16 {%0,%1,%2,%3},[%4];\n"
                 : "=r"(r0), "=r"(r1), "=r"(r2), "=r"(r3) : "r"(addr));
}
__device__ __forceinline__ void ldm_x2(uint32_t& r0, uint32_t& r1, uint32_t addr) {
    asm volatile("ldmatrix.sync.aligned.m8n8.x2.shared.b16 {%0,%1},[%2];\n"
                 : "=r"(r0), "=r"(r1) : "r"(addr));
}
__device__ __forceinline__ void ldm_x2t(uint32_t& r0, uint32_t& r1, uint32_t addr) {
    asm volatile("ldmatrix.sync.aligned.m8n8.x2.trans.shared.b16 {%0,%1},[%2];\n"
                 : "=r"(r0), "=r"(r1) : "r"(addr));
}
__device__ __forceinline__ void mma_bf16(float& c0, float& c1, float& c2, float& c3,
                                         uint32_t a0, uint32_t a1, uint32_t a2, uint32_t a3,
                                         uint32_t b0, uint32_t b1) {
    asm volatile(
        "mma.sync.aligned.m16n8k16.row.col.f32.bf16.bf16.f32 "
        "{%0,%1,%2,%3},{%4,%5,%6,%7},{%8,%9},{%0,%1,%2,%3};\n"
        : "+f"(c0), "+f"(c1), "+f"(c2), "+f"(c3)
        : "r"(a0), "r"(a1), "r"(a2), "r"(a3), "r"(b0), "r"(b1));
}
__device__ __forceinline__ float gelu_exact(float v) {
    return 0.5f * v * (1.f + erff(v * 0.7071067811865476f));
}
__device__ __forceinline__ uint32_t packbf(float a, float b) {
    __nv_bfloat162 t = __floats2bfloat162_rn(a, b);
    return *reinterpret_cast<uint32_t*>(&t);
}

// ---------------- LayerNorm (LN2: plain rows) ----------------
__global__ void __launch_bounds__(256) ln_kernel(const float* __restrict__ src,
                                                 const float* __restrict__ w,
                                                 const float* __restrict__ b,
                                                 __nv_bfloat16* __restrict__ dst) {
    int warp = threadIdx.x >> 5;
    int lane = threadIdx.x & 31;
    int r = blockIdx.x * 8 + warp;
    const float* p = src + (size_t)r * 192;
    float v[6];
    float s = 0.f, s2 = 0.f;
#pragma unroll
    for (int k = 0; k < 6; k++) {
        v[k] = p[lane + 32 * k];
        s += v[k];
        s2 = fmaf(v[k], v[k], s2);
    }
#pragma unroll
    for (int o = 16; o > 0; o >>= 1) {
        s  += __shfl_xor_sync(0xffffffffu, s,  o);
        s2 += __shfl_xor_sync(0xffffffffu, s2, o);
    }
    float mean = s * (1.f / 192.f);
    float var  = s2 * (1.f / 192.f) - mean * mean;
    float rstd = rsqrtf(var + 1e-5f);
    __nv_bfloat16* dp = dst + (size_t)r * 192;
#pragma unroll
    for (int k = 0; k < 6; k++) {
        int c = lane + 32 * k;
        dp[c] = __float2bfloat16((v[k] - mean) * rstd * w[c] + b[c]);
    }
}

// ================= A-resident GEMM (K=192) =================
constexpr int AS_STR = 200;
constexpr int BS_STR = 72;
constexpr int SMEM_A_RES = (128 * AS_STR + 2 * 192 * BS_STR) * 2;

template <int NT, int NGLOB, int MODE>
__global__ void __launch_bounds__(256, 2) gemmA_kernel(const __nv_bfloat16* __restrict__ A,
                                                       const __nv_bfloat16* __restrict__ B,
                                                       const float* __restrict__ bias,
                                                       const float* __restrict__ resid,
                                                       float* __restrict__ outF,
                                                       __nv_bfloat16* __restrict__ outB) {
    extern __shared__ __align__(16) __nv_bfloat16 smem[];
    __nv_bfloat16* As = smem;
    const uint32_t sA = (uint32_t)__cvta_generic_to_shared(As);
    const uint32_t sB = sA + 128 * AS_STR * 2;
    const int tid = threadIdx.x;
    const int m0 = blockIdx.x * 128;

#pragma unroll
    for (int i = 0; i < 12; i++) {
        int c = tid + 256 * i;
        int r = c / 24, co = (c % 24) * 8;
        cp16(sA + (r * AS_STR + co) * 2, A + (size_t)(m0 + r) * 192 + co);
    }
    cp_commit();
#pragma unroll
    for (int i = 0; i < 6; i++) {
        int c = tid + 256 * i;
        int k = c >> 3, nn = (c & 7) * 8;
        cp16(sB + (k * BS_STR + nn) * 2, B + (size_t)k * NGLOB + nn);
    }
    cp_commit();

    const int warp = tid >> 5, lane = tid & 31;
    const int wm = warp >> 1, wn = warp & 1;
    const int gid = lane >> 2, tig = lane & 3;
    const int l15 = lane & 15;
    const uint32_t BUFB = 192 * BS_STR * 2;
    uint32_t bufOff = 0;

    for (int nt = 0; nt < NT; nt++) {
        cp_wait<0>();
        __syncthreads();
        if (nt + 1 < NT) {
            uint32_t other = BUFB - bufOff;
            const __nv_bfloat16* Bg = B + (nt + 1) * 64;
#pragma unroll
            for (int i = 0; i < 6; i++) {
                int c = tid + 256 * i;
                int k = c >> 3, nn = (c & 7) * 8;
                cp16(sB + other + (k * BS_STR + nn) * 2, Bg + (size_t)k * NGLOB + nn);
            }
            cp_commit();
        }

        float acc[2][4][4] = {};
#pragma unroll
        for (int kb = 0; kb < 192; kb += 16) {
            uint32_t a[2][4];
#pragma unroll
            for (int mi = 0; mi < 2; mi++)
                ldm_x4(a[mi][0], a[mi][1], a[mi][2], a[mi][3],
                       sA + ((wm * 32 + mi * 16 + l15) * AS_STR + kb + (lane >> 4) * 8) * 2);
            uint32_t bfr[4][2];
#pragma unroll
            for (int ni = 0; ni < 4; ni++)
                ldm_x2t(bfr[ni][0], bfr[ni][1],
                        sB + bufOff + ((kb + l15) * BS_STR + wn * 32 + ni * 8) * 2);
#pragma unroll
            for (int mi = 0; mi < 2; mi++)
#pragma unroll
                for (int ni = 0; ni < 4; ni++)
                    mma_bf16(acc[mi][ni][0], acc[mi][ni][1], acc[mi][ni][2], acc[mi][ni][3],
                             a[mi][0], a[mi][1], a[mi][2], a[mi][3],
                             bfr[ni][0], bfr[ni][1]);
        }

#pragma unroll
        for (int mi = 0; mi < 2; mi++) {
#pragma unroll
            for (int ni = 0; ni < 4; ni++) {
                int colg = nt * 64 + wn * 32 + ni * 8 + tig * 2;
                float b0 = __ldg(bias + colg), b1 = __ldg(bias + colg + 1);
#pragma unroll
                for (int hh = 0; hh < 2; hh++) {
                    int row = m0 + wm * 32 + mi * 16 + gid + hh * 8;
                    float v0 = acc[mi][ni][hh * 2 + 0] + b0;
                    float v1 = acc[mi][ni][hh * 2 + 1] + b1;
                    if constexpr (MODE == 1) { v0 = gelu_exact(v0); v1 = gelu_exact(v1); }
                    if constexpr (MODE == 0 || MODE == 1) {
                        __nv_bfloat162 h2;
                        h2.x = __float2bfloat16(v0);
                        h2.y = __float2bfloat16(v1);
                        *reinterpret_cast<__nv_bfloat162*>(outB + (size_t)row * NGLOB + colg) = h2;
                    } else {
                        int yr = maprow(row);
                        float2 xr = *reinterpret_cast<const float2*>(resid + (size_t)yr * 192 + colg);
                        float2 o; o.x = v0 + xr.x; o.y = v1 + xr.y;
                        *reinterpret_cast<float2*>(outF + (size_t)yr * 192 + colg) = o;
                    }
                }
            }
        }
        bufOff = BUFB - bufOff;
    }
}

// ================= fused LN1 + QKV GEMM (M-tile 128, K=192, N=576) =================
__global__ void __launch_bounds__(256, 2) gemmQKV_kernel(const float* __restrict__ x,
                                                         const float* __restrict__ n1w,
                                                         const float* __restrict__ n1b,
                                                         const __nv_bfloat16* __restrict__ B,
                                                         const float* __restrict__ bias,
                                                         __nv_bfloat16* __restrict__ outB) {
    extern __shared__ __align__(16) __nv_bfloat16 smem[];
    __nv_bfloat16* As = smem;
    const uint32_t sA = (uint32_t)__cvta_generic_to_shared(As);
    const uint32_t sB = sA + 128 * AS_STR * 2;
    const int tid = threadIdx.x;
    const int m0 = blockIdx.x * 128;
    const int warp = tid >> 5, lane = tid & 31;

    // issue B tile 0 (flies under the LN phase)
#pragma unroll
    for (int i = 0; i < 6; i++) {
        int c = tid + 256 * i;
        int k = c >> 3, nn = (c & 7) * 8;
        cp16(sB + (k * BS_STR + nn) * 2, B + (size_t)k * 576 + nn);
    }
    cp_commit();

    // LN1 gather: each warp normalizes 16 rows into As
    for (int rr = 0; rr < 16; rr++) {
        int rl = warp * 16 + rr;
        const float* p = x + (size_t)maprow(m0 + rl) * 192;
        float v[6];
        float s = 0.f, s2 = 0.f;
#pragma unroll
        for (int k = 0; k < 6; k++) {
            v[k] = p[lane + 32 * k];
            s += v[k];
            s2 = fmaf(v[k], v[k], s2);
        }
#pragma unroll
        for (int o = 16; o > 0; o >>= 1) {
            s  += __shfl_xor_sync(0xffffffffu, s,  o);
            s2 += __shfl_xor_sync(0xffffffffu, s2, o);
        }
        float mean = s * (1.f / 192.f);
        float var  = s2 * (1.f / 192.f) - mean * mean;
        float rstd = rsqrtf(var + 1e-5f);
#pragma unroll
        for (int k = 0; k < 6; k++) {
            int c = lane + 32 * k;
            As[rl * AS_STR + c] = __float2bfloat16((v[k] - mean) * rstd * n1w[c] + n1b[c]);
        }
    }
    __syncthreads();

    const int wm = warp >> 1, wn = warp & 1;
    const int gid = lane >> 2, tig = lane & 3;
    const int l15 = lane & 15;
    const uint32_t BUFB = 192 * BS_STR * 2;
    uint32_t bufOff = 0;

    for (int nt = 0; nt < 9; nt++) {
        cp_wait<0>();
        __syncthreads();
        if (nt + 1 < 9) {
            uint32_t other = BUFB - bufOff;
            const __nv_bfloat16* Bg = B + (nt + 1) * 64;
#pragma unroll
            for (int i = 0; i < 6; i++) {
                int c = tid + 256 * i;
                int k = c >> 3, nn = (c & 7) * 8;
                cp16(sB + other + (k * BS_STR + nn) * 2, Bg + (size_t)k * 576 + nn);
            }
            cp_commit();
        }

        float acc[2][4][4] = {};
#pragma unroll
        for (int kb = 0; kb < 192; kb += 16) {
            uint32_t a[2][4];
#pragma unroll
            for (int mi = 0; mi < 2; mi++)
                ldm_x4(a[mi][0], a[mi][1], a[mi][2], a[mi][3],
                       sA + ((wm * 32 + mi * 16 + l15) * AS_STR + kb + (lane >> 4) * 8) * 2);
            uint32_t bfr[4][2];
#pragma unroll
            for (int ni = 0; ni < 4; ni++)
                ldm_x2t(bfr[ni][0], bfr[ni][1],
                        sB + bufOff + ((kb + l15) * BS_STR + wn * 32 + ni * 8) * 2);
#pragma unroll
            for (int mi = 0; mi < 2; mi++)
#pragma unroll
                for (int ni = 0; ni < 4; ni++)
                    mma_bf16(acc[mi][ni][0], acc[mi][ni][1], acc[mi][ni][2], acc[mi][ni][3],
                             a[mi][0], a[mi][1], a[mi][2], a[mi][3],
                             bfr[ni][0], bfr[ni][1]);
        }

#pragma unroll
        for (int mi = 0; mi < 2; mi++) {
#pragma unroll
            for (int ni = 0; ni < 4; ni++) {
                int colg = nt * 64 + wn * 32 + ni * 8 + tig * 2;
                float b0 = __ldg(bias + colg), b1 = __ldg(bias + colg + 1);
#pragma unroll
                for (int hh = 0; hh < 2; hh++) {
                    int row = m0 + wm * 32 + mi * 16 + gid + hh * 8;
                    uint32_t pk = packbf(acc[mi][ni][hh * 2] + b0, acc[mi][ni][hh * 2 + 1] + b1);
                    *reinterpret_cast<uint32_t*>(outB + (size_t)row * 576 + colg) = pk;
                }
            }
        }
        bufOff = BUFB - bufOff;
    }
}

// ================= MLP2 GEMM (K=768, N=192): 64x192 tile, 4-stage pipeline =================
constexpr int A2_STR = 40;
constexpr int B2_STR = 200;
constexpr int STG_H  = 64 * A2_STR + 32 * B2_STR;
constexpr int SMEM_K_RES = 4 * STG_H * 2;

__global__ void __launch_bounds__(256, 2) gemmK_kernel(const __nv_bfloat16* __restrict__ A,
                                                       const __nv_bfloat16* __restrict__ B,
                                                       const float* __restrict__ bias,
                                                       float* __restrict__ outF) {
    extern __shared__ __align__(16) __nv_bfloat16 smem[];
    const uint32_t sbase = (uint32_t)__cvta_generic_to_shared(smem);
    const int tid = threadIdx.x;
    const int m0 = blockIdx.x * 64;

    auto issue = [&](int chunk, int stage) {
        int kk = chunk * 32;
        uint32_t st = sbase + stage * STG_H * 2;
        {
            int r = tid >> 2, co = (tid & 3) * 8;
            cp16(st + (r * A2_STR + co) * 2, A + (size_t)(m0 + r) * 768 + kk + co);
        }
#pragma unroll
        for (int i = 0; i < 3; i++) {
            int c = tid + 256 * i;
            int k = c / 24, nn = (c % 24) * 8;
            cp16(st + (64 * A2_STR + k * B2_STR + nn) * 2, B + (size_t)(kk + k) * 192 + nn);
        }
        cp_commit();
    };

    issue(0, 0); issue(1, 1); issue(2, 2);

    const int warp = tid >> 5, lane = tid & 31;
    const int wm = warp >> 2, wn = warp & 3;
    const int gid = lane >> 2, tig = lane & 3;
    const int l15 = lane & 15;

    float acc[2][6][4] = {};

    for (int kc = 0; kc < 24; kc++) {
        if (kc < 22) cp_wait<2>();
        else if (kc == 22) cp_wait<1>();
        else cp_wait<0>();
        __syncthreads();
        if (kc + 3 < 24) issue(kc + 3, (kc + 3) & 3);

        uint32_t st = sbase + (kc & 3) * STG_H * 2;
#pragma unroll
        for (int kb = 0; kb < 32; kb += 16) {
            uint32_t a[2][4];
#pragma unroll
            for (int mi = 0; mi < 2; mi++)
                ldm_x4(a[mi][0], a[mi][1], a[mi][2], a[mi][3],
                       st + ((wm * 32 + mi * 16 + l15) * A2_STR + kb + (lane >> 4) * 8) * 2);
            uint32_t bfr[6][2];
#pragma unroll
            for (int ni = 0; ni < 6; ni++)
                ldm_x2t(bfr[ni][0], bfr[ni][1],
                        st + (64 * A2_STR + (kb + l15) * B2_STR + wn * 48 + ni * 8) * 2);
#pragma unroll
            for (int mi = 0; mi < 2; mi++)
#pragma unroll
                for (int ni = 0; ni < 6; ni++)
                    mma_bf16(acc[mi][ni][0], acc[mi][ni][1], acc[mi][ni][2], acc[mi][ni][3],
                             a[mi][0], a[mi][1], a[mi][2], a[mi][3],
                             bfr[ni][0], bfr[ni][1]);
        }
    }

#pragma unroll
    for (int mi = 0; mi < 2; mi++) {
#pragma unroll
        for (int ni = 0; ni < 6; ni++) {
            int colg = wn * 48 + ni * 8 + tig * 2;
            float b0 = __ldg(bias + colg), b1 = __ldg(bias + colg + 1);
#pragma unroll
            for (int hh = 0; hh < 2; hh++) {
                int row = m0 + wm * 32 + mi * 16 + gid + hh * 8;
                float2 pr = *reinterpret_cast<float2*>(outF + (size_t)row * 192 + colg);
                pr.x += acc[mi][ni][hh * 2 + 0] + b0;
                pr.y += acc[mi][ni][hh * 2 + 1] + b1;
                *reinterpret_cast<float2*>(outF + (size_t)row * 192 + colg) = pr;
            }
        }
    }
}

// ================= tensor-core windowed attention =================
constexpr int SQ = 584;
constexpr int ATT_Q_BYTES = 64 * SQ * 2;
constexpr int ATT_SMEM = ATT_Q_BYTES + 1014 * 4 + 256;

__global__ void __launch_bounds__(384, 1) attn_kernel(const __nv_bfloat16* __restrict__ qkv,
                                                      const float* __restrict__ rpb,
                                                      __nv_bfloat16* __restrict__ outb) {
    extern __shared__ __align__(16) unsigned char smraw[];
    __nv_bfloat16* qkvs = reinterpret_cast<__nv_bfloat16*>(smraw);
    float* rpbh = reinterpret_cast<float*>(smraw + ATT_Q_BYTES);
    int* rid = reinterpret_cast<int*>(smraw + ATT_Q_BYTES + 1014 * 4);
    const uint32_t sQ = (uint32_t)__cvta_generic_to_shared(qkvs);

    const int w = blockIdx.x;
    const int tid = threadIdx.x;

    for (int idx = tid; idx < 15 * SQ / 2; idx += 384)
        reinterpret_cast<uint32_t*>(qkvs)[49 * SQ / 2 + idx] = 0;
    const __nv_bfloat16* src = qkv + (size_t)w * 49 * 576;
#pragma unroll
    for (int i = 0; i < 10; i++) {
        int idx = tid + 384 * i;
        if (idx < 3528) {
            int r = idx / 72, c8 = (idx % 72) * 8;
            cp16(sQ + (r * SQ + c8) * 2, src + (size_t)r * 576 + c8);
        }
    }
    cp_commit();
    for (int idx = tid; idx < 1014; idx += 384) {
        int h = idx / 169, p2 = idx - h * 169;
        rpbh[idx] = rpb[p2 * 6 + h];
    }
    if (tid < 49) {
        int wi = w & 1023;
        int wh = wi >> 5, ww = wi & 31;
        int th = tid / 7, tw = tid - th * 7;
        int hs  = wh * 7 + th;
        int ws2 = ww * 7 + tw;
        int hr = hs  < 217 ? 0 : (hs  < 221 ? 1 : 2);
        int wr = ws2 < 217 ? 0 : (ws2 < 221 ? 1 : 2);
        rid[tid] = hr * 3 + wr;
    }
    cp_wait<0>();
    __syncthreads();

    const int warp = tid >> 5, lane = tid & 31;
    const int h = warp >> 1, mh = warp & 1;
    const int gid = lane >> 2, tig = lane & 3;
    const int l15 = lane & 15;
    const int co = h * 32;

    uint32_t aQ[2][2][4];
#pragma unroll
    for (int mi = 0; mi < 2; mi++)
#pragma unroll
        for (int kt = 0; kt < 2; kt++)
            ldm_x4(aQ[mi][kt][0], aQ[mi][kt][1], aQ[mi][kt][2], aQ[mi][kt][3],
                   sQ + ((mh * 32 + mi * 16 + l15) * SQ + co + kt * 16 + (lane >> 4) * 8) * 2);

    float sacc[2][8][4] = {};
#pragma unroll
    for (int kt = 0; kt < 2; kt++) {
        uint32_t bK[8][2];
#pragma unroll
        for (int ni = 0; ni < 8; ni++)
            ldm_x2(bK[ni][0], bK[ni][1],
                   sQ + ((ni * 8 + (l15 & 7)) * SQ + 192 + co + kt * 16 + ((l15 >> 3) & 1) * 8) * 2);
#pragma unroll
        for (int mi = 0; mi < 2; mi++)
#pragma unroll
            for (int ni = 0; ni < 8; ni++)
                mma_bf16(sacc[mi][ni][0], sacc[mi][ni][1], sacc[mi][ni][2], sacc[mi][ni][3],
                         aQ[mi][kt][0], aQ[mi][kt][1], aQ[mi][kt][2], aQ[mi][kt][3],
                         bK[ni][0], bK[ni][1]);
    }

    const float scale = 0.17677669529663687f;
    const float* rp = rpbh + h * 169;
    uint32_t aP[2][4][4];
#pragma unroll
    for (int mi = 0; mi < 2; mi++) {
        int i0 = mh * 32 + mi * 16 + gid;
        int i1 = i0 + 8;
        int ii0 = min(i0, 48), ii1 = min(i1, 48);
        int ih0 = ii0 / 7, iw0 = ii0 - ih0 * 7;
        int ih1 = ii1 / 7, iw1 = ii1 - ih1 * 7;
        int r0 = rid[ii0], r1 = rid[ii1];
        float mx0 = -1e30f, mx1 = -1e30f;
#pragma unroll
        for (int ni = 0; ni < 8; ni++) {
#pragma unroll
            for (int c = 0; c < 2; c++) {
                int j = ni * 8 + tig * 2 + c;
                if (j < 49) {
                    int jh = j / 7, jw = j - jh * 7;
                    int rj = rid[j];
                    float b0 = rp[(ih0 - jh + 6) * 13 + (iw0 - jw + 6)];
                    float b1 = rp[(ih1 - jh + 6) * 13 + (iw1 - jw + 6)];
                    float s0 = sacc[mi][ni][c] * scale + b0 + (r0 != rj ? -100.f : 0.f);
                    float s1 = sacc[mi][ni][2 + c] * scale + b1 + (r1 != rj ? -100.f : 0.f);
                    sacc[mi][ni][c] = s0;
                    sacc[mi][ni][2 + c] = s1;
                    mx0 = fmaxf(mx0, s0);
                    mx1 = fmaxf(mx1, s1);
                } else {
                    sacc[mi][ni][c] = -1e30f;
                    sacc[mi][ni][2 + c] = -1e30f;
                }
            }
        }
        mx0 = fmaxf(mx0, __shfl_xor_sync(0xffffffffu, mx0, 1));
        mx0 = fmaxf(mx0, __shfl_xor_sync(0xffffffffu, mx0, 2));
        mx1 = fmaxf(mx1, __shfl_xor_sync(0xffffffffu, mx1, 1));
        mx1 = fmaxf(mx1, __shfl_xor_sync(0xffffffffu, mx1, 2));
        float sm0 = 0.f, sm1 = 0.f;
#pragma unroll
        for (int ni = 0; ni < 8; ni++) {
#pragma unroll
            for (int c = 0; c < 2; c++) {
                float e0 = __expf(sacc[mi][ni][c] - mx0);
                float e1 = __expf(sacc[mi][ni][2 + c] - mx1);
                sacc[mi][ni][c] = e0;
                sacc[mi][ni][2 + c] = e1;
                sm0 += e0; sm1 += e1;
            }
        }
        sm0 += __shfl_xor_sync(0xffffffffu, sm0, 1);
        sm0 += __shfl_xor_sync(0xffffffffu, sm0, 2);
        sm1 += __shfl_xor_sync(0xffffffffu, sm1, 1);
        sm1 += __shfl_xor_sync(0xffffffffu, sm1, 2);
        float inv0 = 1.f / sm0, inv1 = 1.f / sm1;
#pragma unroll
        for (int kt = 0; kt < 4; kt++) {
            aP[mi][kt][0] = packbf(sacc[mi][2 * kt][0] * inv0,     sacc[mi][2 * kt][1] * inv0);
            aP[mi][kt][1] = packbf(sacc[mi][2 * kt][2] * inv1,     sacc[mi][2 * kt][3] * inv1);
            aP[mi][kt][2] = packbf(sacc[mi][2 * kt + 1][0] * inv0, sacc[mi][2 * kt + 1][1] * inv0);
            aP[mi][kt][3] = packbf(sacc[mi][2 * kt + 1][2] * inv1, sacc[mi][2 * kt + 1][3] * inv1);
        }
    }

    float oacc[2][4][4] = {};
#pragma unroll
    for (int kt = 0; kt < 4; kt++) {
        uint32_t bV[4][2];
#pragma unroll
        for (int ni = 0; ni < 4; ni++)
            ldm_x2t(bV[ni][0], bV[ni][1],
                    sQ + ((kt * 16 + l15) * SQ + 384 + co + ni * 8) * 2);
#pragma unroll
        for (int mi = 0; mi < 2; mi++)
#pragma unroll
            for (int ni = 0; ni < 4; ni++)
                mma_bf16(oacc[mi][ni][0], oacc[mi][ni][1], oacc[mi][ni][2], oacc[mi][ni][3],
                         aP[mi][kt][0], aP[mi][kt][1], aP[mi][kt][2], aP[mi][kt][3],
                         bV[ni][0], bV[ni][1]);
    }

#pragma unroll
    for (int mi = 0; mi < 2; mi++) {
        int i0 = mh * 32 + mi * 16 + gid;
        if (i0 < 49) {
            __nv_bfloat16* op = outb + (size_t)(w * 49 + i0) * 192 + co;
#pragma unroll
            for (int ni = 0; ni < 4; ni++) {
                uint32_t pk = packbf(oacc[mi][ni][0], oacc[mi][ni][1]);
                *reinterpret_cast<uint32_t*>(op + ni * 8 + tig * 2) = pk;
            }
        }
        int i1 = i0 + 8;
        if (i1 < 49) {
            __nv_bfloat16* op = outb + (size_t)(w * 49 + i1) * 192 + co;
#pragma unroll
            for (int ni = 0; ni < 4; ni++) {
                uint32_t pk = packbf(oacc[mi][ni][2], oacc[mi][ni][3]);
                *reinterpret_cast<uint32_t*>(op + ni * 8 + tig * 2) = pk;
            }
        }
    }
}

// ---------------- launch ----------------
extern "C" void kernel_launch(void* const* d_in, const int* in_sizes, int n_in,
                              void* d_out, int out_size) {
    const float* x      = (const float*)d_in[0];
    const float* qkv_w  = (const float*)d_in[3];
    const float* qkv_b  = (const float*)d_in[4];
    const float* proj_w = (const float*)d_in[5];
    const float* proj_b = (const float*)d_in[6];
    const float* rpb    = (const float*)d_in[7];
    const float* n1w    = (const float*)d_in[8];
    const float* n1b    = (const float*)d_in[9];
    const float* n2w    = (const float*)d_in[10];
    const float* n2b    = (const float*)d_in[11];
    const float* w1     = (const float*)d_in[12];
    const float* b1     = (const float*)d_in[13];
    const float* w2     = (const float*)d_in[14];
    const float* b2     = (const float*)d_in[15];
    float* out = (float*)d_out;

    void* p;
    cudaGetSymbolAddress(&p, g_qkv);   __nv_bfloat16* qkvb  = (__nv_bfloat16*)p;
    cudaGetSymbolAddress(&p, g_attn);  __nv_bfloat16* attnb = (__nv_bfloat16*)p;
    cudaGetSymbolAddress(&p, g_m);     __nv_bfloat16* mbuf  = (__nv_bfloat16*)p;
    cudaGetSymbolAddress(&p, g_hid);   __nv_bfloat16* hidb  = (__nv_bfloat16*)p;
    cudaGetSymbolAddress(&p, g_wqkv);  __nv_bfloat16* wqkv  = (__nv_bfloat16*)p;
    cudaGetSymbolAddress(&p, g_wproj); __nv_bfloat16* wproj = (__nv_bfloat16*)p;
    cudaGetSymbolAddress(&p, g_w1);    __nv_bfloat16* w1b   = (__nv_bfloat16*)p;
    cudaGetSymbolAddress(&p, g_w2);    __nv_bfloat16* w2b   = (__nv_bfloat16*)p;

    cudaFuncSetAttribute(gemmQKV_kernel,
                         cudaFuncAttributeMaxDynamicSharedMemorySize, SMEM_A_RES);
    cudaFuncSetAttribute(gemmA_kernel<3, 192, 2>,
                         cudaFuncAttributeMaxDynamicSharedMemorySize, SMEM_A_RES);
    cudaFuncSetAttribute(gemmA_kernel<12, 768, 1>,
                         cudaFuncAttributeMaxDynamicSharedMemorySize, SMEM_A_RES);
    cudaFuncSetAttribute(gemmK_kernel,
                         cudaFuncAttributeMaxDynamicSharedMemorySize, SMEM_K_RES);
    cudaFuncSetAttribute(attn_kernel,
                         cudaFuncAttributeMaxDynamicSharedMemorySize, ATT_SMEM);

    // weight casts (tiny)
    convert_kernel<<<(192 * 576 + 255) / 256, 256>>>(qkv_w, wqkv, 192 * 576);
    convert_kernel<<<(192 * 192 + 255) / 256, 256>>>(proj_w, wproj, 192 * 192);
    convert_kernel<<<(192 * 768 + 255) / 256, 256>>>(w1, w1b, 192 * 768);
    convert_kernel<<<(768 * 192 + 255) / 256, 256>>>(w2, w2b, 768 * 192);

    // 1) fused LN1 + QKV GEMM  [T,192]@[192,576]
    gemmQKV_kernel<<<T_TOK / 128, 256, SMEM_A_RES>>>(x, n1w, n1b, wqkv, qkv_b, qkvb);

    // 2) tensor-core windowed attention (one CTA per window)
    attn_kernel<<<T_TOK / 49, 384, ATT_SMEM>>>(qkvb, rpb, attnb);

    // 3) proj GEMM + window-reverse scatter + shortcut add -> d_out
    gemmA_kernel<3, 192, 2><<<T_TOK / 128, 256, SMEM_A_RES>>>(attnb, wproj, proj_b, x, out, nullptr);

    // 4) LN2
    ln_kernel<<<T_TOK / 8, 256>>>(out, n2w, n2b, mbuf);

    // 5) MLP GEMM1 + GELU
    gemmA_kernel<12, 768, 1><<<T_TOK / 128, 256, SMEM_A_RES>>>(mbuf, w1b, b1, nullptr, nullptr, hidb);

    // 6) MLP GEMM2 + residual (in-place on d_out)
    gemmK_kernel<<<T_TOK / 64, 256, SMEM_K_RES>>>(hidb, w2b, b2, out);

    (void)in_sizes; (void)n_in; (void)out_size;
}

// round 15
// speedup vs baseline: 1.5059x; 1.5059x over previous
#include <cuda_runtime.h>
#include <cuda_bf16.h>
#include <cstdint>
#include <math.h>

// ---------------- problem constants ----------------
constexpr int T_TOK = 401408;      // 8*224*224 tokens (= 8192 windows * 49)

// ---------------- scratch (device globals: no cudaMalloc allowed) ----------------
__device__ __align__(16) __nv_bfloat16 g_winX[(size_t)T_TOK * 192];
__device__ __align__(16) __nv_bfloat16 g_qkv [(size_t)T_TOK * 576];
__device__ __align__(16) __nv_bfloat16 g_attn[(size_t)T_TOK * 192];
__device__ __align__(16) __nv_bfloat16 g_m   [(size_t)T_TOK * 192];
__device__ __align__(16) __nv_bfloat16 g_hid [(size_t)T_TOK * 768];
__device__ __align__(16) __nv_bfloat16 g_wqkv[192 * 576];
__device__ __align__(16) __nv_bfloat16 g_wproj[192 * 192];
__device__ __align__(16) __nv_bfloat16 g_w1  [192 * 768];
__device__ __align__(16) __nv_bfloat16 g_w2  [768 * 192];

// ---------------- row mapping: window row -> image row ----------------
__device__ __forceinline__ int maprow(int r) {
    int w  = r / 49;
    int t  = r - w * 49;
    int wb = w >> 10;
    int wi = w & 1023;
    int wh = wi >> 5;
    int ww = wi & 31;
    int th = t / 7;
    int tw = t - th * 7;
    int h  = wh * 7 + th + 3; if (h  >= 224) h  -= 224;
    int wc = ww * 7 + tw + 3; if (wc >= 224) wc -= 224;
    return wb * 50176 + h * 224 + wc;
}

// ---------------- merged weight cast: all four weight matrices in one launch ----------------
constexpr int N_QKVW = 192 * 576;   // 110592
constexpr int N_PROJ = 192 * 192;   // 36864
constexpr int N_W1   = 192 * 768;   // 147456
constexpr int N_W2   = 768 * 192;   // 147456
constexpr int N_ALL  = N_QKVW + N_PROJ + N_W1 + N_W2;  // 442368 = 1728*256

__global__ void convert_all_kernel(const float* __restrict__ qkv_w,
                                   const float* __restrict__ proj_w,
                                   const float* __restrict__ w1,
                                   const float* __restrict__ w2,
                                   __nv_bfloat16* __restrict__ wqkv,
                                   __nv_bfloat16* __restrict__ wproj,
                                   __nv_bfloat16* __restrict__ w1b,
                                   __nv_bfloat16* __restrict__ w2b) {
    int i = blockIdx.x * blockDim.x + threadIdx.x;
    if (i < N_QKVW) {
        wqkv[i] = __float2bfloat16(qkv_w[i]);
    } else if (i < N_QKVW + N_PROJ) {
        int j = i - N_QKVW;
        wproj[j] = __float2bfloat16(proj_w[j]);
    } else if (i < N_QKVW + N_PROJ + N_W1) {
        int j = i - N_QKVW - N_PROJ;
        w1b[j] = __float2bfloat16(w1[j]);
    } else if (i < N_ALL) {
        int j = i - N_QKVW - N_PROJ - N_W1;
        w2b[j] = __float2bfloat16(w2[j]);
    }
}

__device__ __forceinline__ void cp16(uint32_t smaddr, const void* g) {
    asm volatile("cp.async.cg.shared.global [%0],[%1],16;\n" :: "r"(smaddr), "l"(g));
}
__device__ __forceinline__ void cp_commit() { asm volatile("cp.async.commit_group;\n"); }
template <int N> __device__ __forceinline__ void cp_wait() {
    asm volatile("cp.async.wait_group %0;\n" :: "n"(N));
}
__device__ __forceinline__ void ldm_x4(uint32_t& r0, uint32_t& r1, uint32_t& r2, uint32_t& r3,
                                       uint32_t addr) {
    asm volatile("ldmatrix.sync.aligned.m8n8.x4.shared.b16 {%0,%1,%2,%3},[%4];\n"
                 : "=r"(r0), "=r"(r1), "=r"(r2), "=r"(r3) : "r"(addr));
}
__device__ __forceinline__ void ldm_x2(uint32_t& r0, uint32_t& r1, uint32_t addr) {
    asm volatile("ldmatrix.sync.aligned.m8n8.x2.shared.b16 {%0,%1},[%2];\n"
                 : "=r"(r0), "=r"(r1) : "r"(addr));
}
__device__ __forceinline__ void ldm_x2t(uint32_t& r0, uint32_t& r1, uint32_t addr) {
    asm volatile("ldmatrix.sync.aligned.m8n8.x2.trans.shared.b16 {%0,%1},[%2];\n"
                 : "=r"(r0), "=r"(r1) : "r"(addr));
}
__device__ __forceinline__ void mma_bf16(float& c0, float& c1, float& c2, float& c3,
                                         uint32_t a0, uint32_t a1, uint32_t a2, uint32_t a3,
                                         uint32_t b0, uint32_t b1) {
    asm volatile(
        "mma.sync.aligned.m16n8k16.row.col.f32.bf16.bf16.f32 "
        "{%0,%1,%2,%3},{%4,%5,%6,%7},{%8,%9},{%0,%1,%2,%3};\n"
        : "+f"(c0), "+f"(c1), "+f"(c2), "+f"(c3)
        : "r"(a0), "r"(a1), "r"(a2), "r"(a3), "r"(b0), "r"(b1));
}
__device__ __forceinline__ float gelu_exact(float v) {
    return 0.5f * v * (1.f + erff(v * 0.7071067811865476f));
}
__device__ __forceinline__ uint32_t packbf(float a, float b) {
    __nv_bfloat162 t = __floats2bfloat162_rn(a, b);
    return *reinterpret_cast<uint32_t*>(&t);
}

// ---------------- LayerNorm (optionally gathering through roll+window map) ----------------
__global__ void __launch_bounds__(256) ln_kernel(const float* __restrict__ src,
                                                 const float* __restrict__ w,
                                                 const float* __restrict__ b,
                                                 __nv_bfloat16* __restrict__ dst,
                                                 int gather) {
    int warp = threadIdx.x >> 5;
    int lane = threadIdx.x & 31;
    int r = blockIdx.x * 8 + warp;
    int srow = gather ? maprow(r) : r;
    const float* p = src + (size_t)srow * 192;
    float v[6];
    float s = 0.f, s2 = 0.f;
#pragma unroll
    for (int k = 0; k < 6; k++) {
        v[k] = p[lane + 32 * k];
        s += v[k];
        s2 = fmaf(v[k], v[k], s2);
    }
#pragma unroll
    for (int o = 16; o > 0; o >>= 1) {
        s  += __shfl_xor_sync(0xffffffffu, s,  o);
        s2 += __shfl_xor_sync(0xffffffffu, s2, o);
    }
    float mean = s * (1.f / 192.f);
    float var  = s2 * (1.f / 192.f) - mean * mean;
    float rstd = rsqrtf(var + 1e-5f);
    __nv_bfloat16* dp = dst + (size_t)r * 192;
#pragma unroll
    for (int k = 0; k < 6; k++) {
        int c = lane + 32 * k;
        dp[c] = __float2bfloat16((v[k] - mean) * rstd * w[c] + b[c]);
    }
}

// ================= A-resident GEMM (K=192) =================
constexpr int AS_STR = 200;
constexpr int BS_STR = 72;
constexpr int SMEM_A_RES = (128 * AS_STR + 2 * 192 * BS_STR) * 2;

template <int NT, int NGLOB, int MODE>
__global__ void __launch_bounds__(256, 2) gemmA_kernel(const __nv_bfloat16* __restrict__ A,
                                                       const __nv_bfloat16* __restrict__ B,
                                                       const float* __restrict__ bias,
                                                       const float* __restrict__ resid,
                                                       float* __restrict__ outF,
                                                       __nv_bfloat16* __restrict__ outB) {
    extern __shared__ __align__(16) __nv_bfloat16 smem[];
    __nv_bfloat16* As = smem;
    const uint32_t sA = (uint32_t)__cvta_generic_to_shared(As);
    const uint32_t sB = sA + 128 * AS_STR * 2;
    const int tid = threadIdx.x;
    const int m0 = blockIdx.x * 128;

#pragma unroll
    for (int i = 0; i < 12; i++) {
        int c = tid + 256 * i;
        int r = c / 24, co = (c % 24) * 8;
        cp16(sA + (r * AS_STR + co) * 2, A + (size_t)(m0 + r) * 192 + co);
    }
    cp_commit();
#pragma unroll
    for (int i = 0; i < 6; i++) {
        int c = tid + 256 * i;
        int k = c >> 3, nn = (c & 7) * 8;
        cp16(sB + (k * BS_STR + nn) * 2, B + (size_t)k * NGLOB + nn);
    }
    cp_commit();

    const int warp = tid >> 5, lane = tid & 31;
    const int wm = warp >> 1, wn = warp & 1;
    const int gid = lane >> 2, tig = lane & 3;
    const int l15 = lane & 15;
    const uint32_t BUFB = 192 * BS_STR * 2;
    uint32_t bufOff = 0;

    for (int nt = 0; nt < NT; nt++) {
        cp_wait<0>();
        __syncthreads();
        if (nt + 1 < NT) {
            uint32_t other = BUFB - bufOff;
            const __nv_bfloat16* Bg = B + (nt + 1) * 64;
#pragma unroll
            for (int i = 0; i < 6; i++) {
                int c = tid + 256 * i;
                int k = c >> 3, nn = (c & 7) * 8;
                cp16(sB + other + (k * BS_STR + nn) * 2, Bg + (size_t)k * NGLOB + nn);
            }
            cp_commit();
        }

        float acc[2][4][4] = {};
#pragma unroll
        for (int kb = 0; kb < 192; kb += 16) {
            uint32_t a[2][4];
#pragma unroll
            for (int mi = 0; mi < 2; mi++)
                ldm_x4(a[mi][0], a[mi][1], a[mi][2], a[mi][3],
                       sA + ((wm * 32 + mi * 16 + l15) * AS_STR + kb + (lane >> 4) * 8) * 2);
            uint32_t bfr[4][2];
#pragma unroll
            for (int ni = 0; ni < 4; ni++)
                ldm_x2t(bfr[ni][0], bfr[ni][1],
                        sB + bufOff + ((kb + l15) * BS_STR + wn * 32 + ni * 8) * 2);
#pragma unroll
            for (int mi = 0; mi < 2; mi++)
#pragma unroll
                for (int ni = 0; ni < 4; ni++)
                    mma_bf16(acc[mi][ni][0], acc[mi][ni][1], acc[mi][ni][2], acc[mi][ni][3],
                             a[mi][0], a[mi][1], a[mi][2], a[mi][3],
                             bfr[ni][0], bfr[ni][1]);
        }

#pragma unroll
        for (int mi = 0; mi < 2; mi++) {
#pragma unroll
            for (int ni = 0; ni < 4; ni++) {
                int colg = nt * 64 + wn * 32 + ni * 8 + tig * 2;
                float b0 = __ldg(bias + colg), b1 = __ldg(bias + colg + 1);
#pragma unroll
                for (int hh = 0; hh < 2; hh++) {
                    int row = m0 + wm * 32 + mi * 16 + gid + hh * 8;
                    float v0 = acc[mi][ni][hh * 2 + 0] + b0;
                    float v1 = acc[mi][ni][hh * 2 + 1] + b1;
                    if constexpr (MODE == 1) { v0 = gelu_exact(v0); v1 = gelu_exact(v1); }
                    if constexpr (MODE == 0 || MODE == 1) {
                        __nv_bfloat162 h2;
                        h2.x = __float2bfloat16(v0);
                        h2.y = __float2bfloat16(v1);
                        *reinterpret_cast<__nv_bfloat162*>(outB + (size_t)row * NGLOB + colg) = h2;
                    } else {
                        int yr = maprow(row);
                        float2 xr = *reinterpret_cast<const float2*>(resid + (size_t)yr * 192 + colg);
                        float2 o; o.x = v0 + xr.x; o.y = v1 + xr.y;
                        *reinterpret_cast<float2*>(outF + (size_t)yr * 192 + colg) = o;
                    }
                }
            }
        }
        bufOff = BUFB - bufOff;
    }
}

// ================= MLP2 GEMM (K=768, N=192): 64x192 tile, 4-stage pipeline =================
constexpr int A2_STR = 40;
constexpr int B2_STR = 200;
constexpr int STG_H  = 64 * A2_STR + 32 * B2_STR;
constexpr int SMEM_K_RES = 4 * STG_H * 2;

__global__ void __launch_bounds__(256, 2) gemmK_kernel(const __nv_bfloat16* __restrict__ A,
                                                       const __nv_bfloat16* __restrict__ B,
                                                       const float* __restrict__ bias,
                                                       float* __restrict__ outF) {
    extern __shared__ __align__(16) __nv_bfloat16 smem[];
    const uint32_t sbase = (uint32_t)__cvta_generic_to_shared(smem);
    const int tid = threadIdx.x;
    const int m0 = blockIdx.x * 64;

    auto issue = [&](int chunk, int stage) {
        int kk = chunk * 32;
        uint32_t st = sbase + stage * STG_H * 2;
        {
            int r = tid >> 2, co = (tid & 3) * 8;
            cp16(st + (r * A2_STR + co) * 2, A + (size_t)(m0 + r) * 768 + kk + co);
        }
#pragma unroll
        for (int i = 0; i < 3; i++) {
            int c = tid + 256 * i;
            int k = c / 24, nn = (c % 24) * 8;
            cp16(st + (64 * A2_STR + k * B2_STR + nn) * 2, B + (size_t)(kk + k) * 192 + nn);
        }
        cp_commit();
    };

    issue(0, 0); issue(1, 1); issue(2, 2);

    const int warp = tid >> 5, lane = tid & 31;
    const int wm = warp >> 2, wn = warp & 3;
    const int gid = lane >> 2, tig = lane & 3;
    const int l15 = lane & 15;

    float acc[2][6][4] = {};

    for (int kc = 0; kc < 24; kc++) {
        if (kc < 22) cp_wait<2>();
        else if (kc == 22) cp_wait<1>();
        else cp_wait<0>();
        __syncthreads();
        if (kc + 3 < 24) issue(kc + 3, (kc + 3) & 3);

        uint32_t st = sbase + (kc & 3) * STG_H * 2;
#pragma unroll
        for (int kb = 0; kb < 32; kb += 16) {
            uint32_t a[2][4];
#pragma unroll
            for (int mi = 0; mi < 2; mi++)
                ldm_x4(a[mi][0], a[mi][1], a[mi][2], a[mi][3],
                       st + ((wm * 32 + mi * 16 + l15) * A2_STR + kb + (lane >> 4) * 8) * 2);
            uint32_t bfr[6][2];
#pragma unroll
            for (int ni = 0; ni < 6; ni++)
                ldm_x2t(bfr[ni][0], bfr[ni][1],
                        st + (64 * A2_STR + (kb + l15) * B2_STR + wn * 48 + ni * 8) * 2);
#pragma unroll
            for (int mi = 0; mi < 2; mi++)
#pragma unroll
                for (int ni = 0; ni < 6; ni++)
                    mma_bf16(acc[mi][ni][0], acc[mi][ni][1], acc[mi][ni][2], acc[mi][ni][3],
                             a[mi][0], a[mi][1], a[mi][2], a[mi][3],
                             bfr[ni][0], bfr[ni][1]);
        }
    }

#pragma unroll
    for (int mi = 0; mi < 2; mi++) {
#pragma unroll
        for (int ni = 0; ni < 6; ni++) {
            int colg = wn * 48 + ni * 8 + tig * 2;
            float b0 = __ldg(bias + colg), b1 = __ldg(bias + colg + 1);
#pragma unroll
            for (int hh = 0; hh < 2; hh++) {
                int row = m0 + wm * 32 + mi * 16 + gid + hh * 8;
                float2 pr = *reinterpret_cast<float2*>(outF + (size_t)row * 192 + colg);
                pr.x += acc[mi][ni][hh * 2 + 0] + b0;
                pr.y += acc[mi][ni][hh * 2 + 1] + b1;
                *reinterpret_cast<float2*>(outF + (size_t)row * 192 + colg) = pr;
            }
        }
    }
}

// ================= tensor-core windowed attention =================
constexpr int SQ = 584;
constexpr int ATT_Q_BYTES = 64 * SQ * 2;
constexpr int ATT_SMEM = ATT_Q_BYTES + 1014 * 4 + 256;

__global__ void __launch_bounds__(384, 1) attn_kernel(const __nv_bfloat16* __restrict__ qkv,
                                                      const float* __restrict__ rpb,
                                                      __nv_bfloat16* __restrict__ outb) {
    extern __shared__ __align__(16) unsigned char smraw[];
    __nv_bfloat16* qkvs = reinterpret_cast<__nv_bfloat16*>(smraw);
    float* rpbh = reinterpret_cast<float*>(smraw + ATT_Q_BYTES);
    int* rid = reinterpret_cast<int*>(smraw + ATT_Q_BYTES + 1014 * 4);
    const uint32_t sQ = (uint32_t)__cvta_generic_to_shared(qkvs);

    const int w = blockIdx.x;
    const int tid = threadIdx.x;

    for (int idx = tid; idx < 15 * SQ / 2; idx += 384)
        reinterpret_cast<uint32_t*>(qkvs)[49 * SQ / 2 + idx] = 0;
    const __nv_bfloat16* src = qkv + (size_t)w * 49 * 576;
#pragma unroll
    for (int i = 0; i < 10; i++) {
        int idx = tid + 384 * i;
        if (idx < 3528) {
            int r = idx / 72, c8 = (idx % 72) * 8;
            cp16(sQ + (r * SQ + c8) * 2, src + (size_t)r * 576 + c8);
        }
    }
    cp_commit();
    for (int idx = tid; idx < 1014; idx += 384) {
        int h = idx / 169, p2 = idx - h * 169;
        rpbh[idx] = rpb[p2 * 6 + h];
    }
    if (tid < 49) {
        int wi = w & 1023;
        int wh = wi >> 5, ww = wi & 31;
        int th = tid / 7, tw = tid - th * 7;
        int hs  = wh * 7 + th;
        int ws2 = ww * 7 + tw;
        int hr = hs  < 217 ? 0 : (hs  < 221 ? 1 : 2);
        int wr = ws2 < 217 ? 0 : (ws2 < 221 ? 1 : 2);
        rid[tid] = hr * 3 + wr;
    }
    cp_wait<0>();
    __syncthreads();

    const int warp = tid >> 5, lane = tid & 31;
    const int h = warp >> 1, mh = warp & 1;
    const int gid = lane >> 2, tig = lane & 3;
    const int l15 = lane & 15;
    const int co = h * 32;

    uint32_t aQ[2][2][4];
#pragma unroll
    for (int mi = 0; mi < 2; mi++)
#pragma unroll
        for (int kt = 0; kt < 2; kt++)
            ldm_x4(aQ[mi][kt][0], aQ[mi][kt][1], aQ[mi][kt][2], aQ[mi][kt][3],
                   sQ + ((mh * 32 + mi * 16 + l15) * SQ + co + kt * 16 + (lane >> 4) * 8) * 2);

    float sacc[2][8][4] = {};
#pragma unroll
    for (int kt = 0; kt < 2; kt++) {
        uint32_t bK[8][2];
#pragma unroll
        for (int ni = 0; ni < 8; ni++)
            ldm_x2(bK[ni][0], bK[ni][1],
                   sQ + ((ni * 8 + (l15 & 7)) * SQ + 192 + co + kt * 16 + ((l15 >> 3) & 1) * 8) * 2);
#pragma unroll
        for (int mi = 0; mi < 2; mi++)
#pragma unroll
            for (int ni = 0; ni < 8; ni++)
                mma_bf16(sacc[mi][ni][0], sacc[mi][ni][1], sacc[mi][ni][2], sacc[mi][ni][3],
                         aQ[mi][kt][0], aQ[mi][kt][1], aQ[mi][kt][2], aQ[mi][kt][3],
                         bK[ni][0], bK[ni][1]);
    }

    const float scale = 0.17677669529663687f;
    const float* rp = rpbh + h * 169;
    uint32_t aP[2][4][4];
#pragma unroll
    for (int mi = 0; mi < 2; mi++) {
        int i0 = mh * 32 + mi * 16 + gid;
        int i1 = i0 + 8;
        int ii0 = min(i0, 48), ii1 = min(i1, 48);
        int ih0 = ii0 / 7, iw0 = ii0 - ih0 * 7;
        int ih1 = ii1 / 7, iw1 = ii1 - ih1 * 7;
        int r0 = rid[ii0], r1 = rid[ii1];
        float mx0 = -1e30f, mx1 = -1e30f;
#pragma unroll
        for (int ni = 0; ni < 8; ni++) {
#pragma unroll
            for (int c = 0; c < 2; c++) {
                int j = ni * 8 + tig * 2 + c;
                if (j < 49) {
                    int jh = j / 7, jw = j - jh * 7;
                    int rj = rid[j];
                    float b0 = rp[(ih0 - jh + 6) * 13 + (iw0 - jw + 6)];
                    float b1 = rp[(ih1 - jh + 6) * 13 + (iw1 - jw + 6)];
                    float s0 = sacc[mi][ni][c] * scale + b0 + (r0 != rj ? -100.f : 0.f);
                    float s1 = sacc[mi][ni][2 + c] * scale + b1 + (r1 != rj ? -100.f : 0.f);
                    sacc[mi][ni][c] = s0;
                    sacc[mi][ni][2 + c] = s1;
                    mx0 = fmaxf(mx0, s0);
                    mx1 = fmaxf(mx1, s1);
                } else {
                    sacc[mi][ni][c] = -1e30f;
                    sacc[mi][ni][2 + c] = -1e30f;
                }
            }
        }
        mx0 = fmaxf(mx0, __shfl_xor_sync(0xffffffffu, mx0, 1));
        mx0 = fmaxf(mx0, __shfl_xor_sync(0xffffffffu, mx0, 2));
        mx1 = fmaxf(mx1, __shfl_xor_sync(0xffffffffu, mx1, 1));
        mx1 = fmaxf(mx1, __shfl_xor_sync(0xffffffffu, mx1, 2));
        float sm0 = 0.f, sm1 = 0.f;
#pragma unroll
        for (int ni = 0; ni < 8; ni++) {
#pragma unroll
            for (int c = 0; c < 2; c++) {
                float e0 = __expf(sacc[mi][ni][c] - mx0);
                float e1 = __expf(sacc[mi][ni][2 + c] - mx1);
                sacc[mi][ni][c] = e0;
                sacc[mi][ni][2 + c] = e1;
                sm0 += e0; sm1 += e1;
            }
        }
        sm0 += __shfl_xor_sync(0xffffffffu, sm0, 1);
        sm0 += __shfl_xor_sync(0xffffffffu, sm0, 2);
        sm1 += __shfl_xor_sync(0xffffffffu, sm1, 1);
        sm1 += __shfl_xor_sync(0xffffffffu, sm1, 2);
        float inv0 = 1.f / sm0, inv1 = 1.f / sm1;
#pragma unroll
        for (int kt = 0; kt < 4; kt++) {
            aP[mi][kt][0] = packbf(sacc[mi][2 * kt][0] * inv0,     sacc[mi][2 * kt][1] * inv0);
            aP[mi][kt][1] = packbf(sacc[mi][2 * kt][2] * inv1,     sacc[mi][2 * kt][3] * inv1);
            aP[mi][kt][2] = packbf(sacc[mi][2 * kt + 1][0] * inv0, sacc[mi][2 * kt + 1][1] * inv0);
            aP[mi][kt][3] = packbf(sacc[mi][2 * kt + 1][2] * inv1, sacc[mi][2 * kt + 1][3] * inv1);
        }
    }

    float oacc[2][4][4] = {};
#pragma unroll
    for (int kt = 0; kt < 4; kt++) {
        uint32_t bV[4][2];
#pragma unroll
        for (int ni = 0; ni < 4; ni++)
            ldm_x2t(bV[ni][0], bV[ni][1],
                    sQ + ((kt * 16 + l15) * SQ + 384 + co + ni * 8) * 2);
#pragma unroll
        for (int mi = 0; mi < 2; mi++)
#pragma unroll
            for (int ni = 0; ni < 4; ni++)
                mma_bf16(oacc[mi][ni][0], oacc[mi][ni][1], oacc[mi][ni][2], oacc[mi][ni][3],
                         aP[mi][kt][0], aP[mi][kt][1], aP[mi][kt][2], aP[mi][kt][3],
                         bV[ni][0], bV[ni][1]);
    }

#pragma unroll
    for (int mi = 0; mi < 2; mi++) {
        int i0 = mh * 32 + mi * 16 + gid;
        if (i0 < 49) {
            __nv_bfloat16* op = outb + (size_t)(w * 49 + i0) * 192 + co;
#pragma unroll
            for (int ni = 0; ni < 4; ni++) {
                uint32_t pk = packbf(oacc[mi][ni][0], oacc[mi][ni][1]);
                *reinterpret_cast<uint32_t*>(op + ni * 8 + tig * 2) = pk;
            }
        }
        int i1 = i0 + 8;
        if (i1 < 49) {
            __nv_bfloat16* op = outb + (size_t)(w * 49 + i1) * 192 + co;
#pragma unroll
            for (int ni = 0; ni < 4; ni++) {
                uint32_t pk = packbf(oacc[mi][ni][2], oacc[mi][ni][3]);
                *reinterpret_cast<uint32_t*>(op + ni * 8 + tig * 2) = pk;
            }
        }
    }
}

// ---------------- launch ----------------
extern "C" void kernel_launch(void* const* d_in, const int* in_sizes, int n_in,
                              void* d_out, int out_size) {
    const float* x      = (const float*)d_in[0];
    const float* qkv_w  = (const float*)d_in[3];
    const float* qkv_b  = (const float*)d_in[4];
    const float* proj_w = (const float*)d_in[5];
    const float* proj_b = (const float*)d_in[6];
    const float* rpb    = (const float*)d_in[7];
    const float* n1w    = (const float*)d_in[8];
    const float* n1b    = (const float*)d_in[9];
    const float* n2w    = (const float*)d_in[10];
    const float* n2b    = (const float*)d_in[11];
    const float* w1     = (const float*)d_in[12];
    const float* b1     = (const float*)d_in[13];
    const float* w2     = (const float*)d_in[14];
    const float* b2     = (const float*)d_in[15];
    float* out = (float*)d_out;

    void* p;
    cudaGetSymbolAddress(&p, g_winX);  __nv_bfloat16* winX  = (__nv_bfloat16*)p;
    cudaGetSymbolAddress(&p, g_qkv);   __nv_bfloat16* qkvb  = (__nv_bfloat16*)p;
    cudaGetSymbolAddress(&p, g_attn);  __nv_bfloat16* attnb = (__nv_bfloat16*)p;
    cudaGetSymbolAddress(&p, g_m);     __nv_bfloat16* mbuf  = (__nv_bfloat16*)p;
    cudaGetSymbolAddress(&p, g_hid);   __nv_bfloat16* hidb  = (__nv_bfloat16*)p;
    cudaGetSymbolAddress(&p, g_wqkv);  __nv_bfloat16* wqkv  = (__nv_bfloat16*)p;
    cudaGetSymbolAddress(&p, g_wproj); __nv_bfloat16* wproj = (__nv_bfloat16*)p;
    cudaGetSymbolAddress(&p, g_w1);    __nv_bfloat16* w1b   = (__nv_bfloat16*)p;
    cudaGetSymbolAddress(&p, g_w2);    __nv_bfloat16* w2b   = (__nv_bfloat16*)p;

    cudaFuncSetAttribute(gemmA_kernel<9, 576, 0>,
                         cudaFuncAttributeMaxDynamicSharedMemorySize, SMEM_A_RES);
    cudaFuncSetAttribute(gemmA_kernel<3, 192, 2>,
                         cudaFuncAttributeMaxDynamicSharedMemorySize, SMEM_A_RES);
    cudaFuncSetAttribute(gemmA_kernel<12, 768, 1>,
                         cudaFuncAttributeMaxDynamicSharedMemorySize, SMEM_A_RES);
    cudaFuncSetAttribute(gemmK_kernel,
                         cudaFuncAttributeMaxDynamicSharedMemorySize, SMEM_K_RES);
    cudaFuncSetAttribute(attn_kernel,
                         cudaFuncAttributeMaxDynamicSharedMemorySize, ATT_SMEM);

    // 0) all weight casts in one launch
    convert_all_kernel<<<N_ALL / 256, 256>>>(qkv_w, proj_w, w1, w2, wqkv, wproj, w1b, w2b);

    // 1) LN1 + roll + window partition
    ln_kernel<<<T_TOK / 8, 256>>>(x, n1w, n1b, winX, 1);

    // 2) QKV GEMM  [T,192]@[192,576]
    gemmA_kernel<9, 576, 0><<<T_TOK / 128, 256, SMEM_A_RES>>>(winX, wqkv, qkv_b, nullptr, nullptr, qkvb);

    // 3) tensor-core windowed attention (one CTA per window)
    attn_kernel<<<T_TOK / 49, 384, ATT_SMEM>>>(qkvb, rpb, attnb);

    // 4) proj GEMM + window-reverse scatter + shortcut add -> d_out
    gemmA_kernel<3, 192, 2><<<T_TOK / 128, 256, SMEM_A_RES>>>(attnb, wproj, proj_b, x, out, nullptr);

    // 5) LN2
    ln_kernel<<<T_TOK / 8, 256>>>(out, n2w, n2b, mbuf, 0);

    // 6) MLP GEMM1 + GELU
    gemmA_kernel<12, 768, 1><<<T_TOK / 128, 256, SMEM_A_RES>>>(mbuf, w1b, b1, nullptr, nullptr, hidb);

    // 7) MLP GEMM2 + residual (in-place on d_out)
    gemmK_kernel<<<T_TOK / 64, 256, SMEM_K_RES>>>(hidb, w2b, b2, out);

    (void)in_sizes; (void)n_in; (void)out_size;
}